// round 12
// baseline (speedup 1.0000x reference)
#include <cuda_runtime.h>
#include <cuda_bf16.h>

#define NN    32768
#define FIN   32
#define HC    64
#define HEADS 4
#define EE    524288
#define ET    (EE + NN)     // 557056 edges incl. self-loops
#define BATCH 64
#define TT    512
#define OUTD  24

// ---------------- scratch (device globals; no allocation) ----------------
__device__ __align__(16) float g_h1[(size_t)NN * 256];     // GAT1 GEMM out
__device__ __align__(16) float g_h2in[(size_t)NN * 256];   // GAT1 agg + b1 + elu
__device__ __align__(16) float g_t2[(size_t)NN * 64];      // GAT2 GEMM out
__device__ __align__(16) float g_seqin[(size_t)NN * 64];   // GAT2 agg + b2 + elu
__device__ __align__(16) float g_gi[(size_t)NN * 192];     // GRU L0 input gates
__device__ __align__(16) float g_as1[NN * 4];
__device__ __align__(16) float g_ad1[NN * 4];
__device__ float g_as2[NN];
__device__ float g_ad2[NN];
__device__ int   g_deg[NN];
__device__ int   g_rowptr[NN + 1];
__device__ int   g_cursor[NN];
__device__ int   g_csr[ET];
__device__ unsigned g_hist_done;

// ---------------- helpers ----------------
__device__ __forceinline__ float lrelu(float v)  { return v > 0.f ? v : 0.2f * v; }
__device__ __forceinline__ float elu1(float v)   { return v > 0.f ? v : (__expf(v) - 1.f); }
// fast tanh (MUFU), |rel err| ~2^-11 << 1e-3 budget
__device__ __forceinline__ float tanhap(float x) {
    float y; asm("tanh.approx.f32 %0, %1;" : "=f"(y) : "f"(x)); return y;
}
__device__ __forceinline__ float sigm(float v)   { return 0.5f * tanhap(0.5f * v) + 0.5f; }
// clamped exp: attention logits are small here; clamp guards overflow only.
__device__ __forceinline__ float eexp(float v)   { return __expf(fminf(v, 60.f)); }

__device__ __forceinline__ float wred(float v) {
#pragma unroll
    for (int o = 16; o; o >>= 1) v += __shfl_xor_sync(0xffffffffu, v, o);
    return v;
}

// packed fp32x2 FMA (sm_103a FFMA2)
__device__ __forceinline__ void fma2(unsigned long long& acc,
                                     unsigned long long a, unsigned long long b) {
    asm("fma.rn.f32x2 %0, %1, %2, %0;" : "+l"(acc) : "l"(a), "l"(b));
}
__device__ __forceinline__ float unpack_sum(unsigned long long v) {
    unsigned lo = (unsigned)v, hi = (unsigned)(v >> 32);
    return __uint_as_float(lo) + __uint_as_float(hi);
}

// ---------------- CSR build: hist + (last block) scan, fused ----------------
__global__ __launch_bounds__(1024) void hist_scan_kernel(const int* __restrict__ ei) {
    int i = blockIdx.x * 1024 + threadIdx.x;       // ET == 544*1024 exactly
    int dst = (i < EE) ? ei[EE + i] : (i - EE);
    atomicAdd(&g_deg[dst], 1);
    __threadfence();
    __shared__ unsigned isLast;
    __shared__ int wsum[32];
    if (threadIdx.x == 0) {
        unsigned v = atomicAdd(&g_hist_done, 1u);
        isLast = (v == gridDim.x - 1) ? 1u : 0u;
    }
    __syncthreads();
    if (!isLast) return;
    if (threadIdx.x == 0) g_hist_done = 0;

    int tid = threadIdx.x;
    int vals[32];
    int base = tid * 32;
    int s = 0;
#pragma unroll
    for (int j = 0; j < 32; j++) {
        int v = g_deg[base + j];
        g_deg[base + j] = 0;
        vals[j] = v; s += v;
    }
    int lane = tid & 31, wid = tid >> 5;
    int inc = s;
#pragma unroll
    for (int o = 1; o < 32; o <<= 1) {
        int y = __shfl_up_sync(0xffffffffu, inc, o);
        if (lane >= o) inc += y;
    }
    if (lane == 31) wsum[wid] = inc;
    __syncthreads();
    if (wid == 0) {
        int v = wsum[lane];
#pragma unroll
        for (int o = 1; o < 32; o <<= 1) {
            int y = __shfl_up_sync(0xffffffffu, v, o);
            if (lane >= o) v += y;
        }
        wsum[lane] = v;
    }
    __syncthreads();
    int off = inc - s + (wid > 0 ? wsum[wid - 1] : 0);
#pragma unroll
    for (int j = 0; j < 32; j++) {
        g_rowptr[base + j] = off;
        g_cursor[base + j] = off;
        off += vals[j];
    }
    if (tid == 1023) g_rowptr[NN] = off;
}

__global__ void scatter_kernel(const int* __restrict__ ei) {
    int i = blockIdx.x * blockDim.x + threadIdx.x;
    if (i >= ET) return;
    int src, dst;
    if (i < EE) { src = ei[i]; dst = ei[EE + i]; }
    else        { src = dst = i - EE; }
    int pos = atomicAdd(&g_cursor[dst], 1);
    g_csr[pos] = src;
}

// ---------------- GAT layer 1: GEMM (4 nodes/warp) + attention coeffs -------
__device__ __forceinline__ void gat1_store_alpha(int node, const float acc[8],
                                                 const float* aS, const float* aD, int lane) {
#pragma unroll
    for (int j = 0; j < 8; j++) g_h1[(size_t)node * 256 + lane + 32 * j] = acc[j];
    float p0 = acc[0] * aS[lane]       + acc[1] * aS[lane + 32];
    float p1 = acc[2] * aS[64 + lane]  + acc[3] * aS[96 + lane];
    float p2 = acc[4] * aS[128 + lane] + acc[5] * aS[160 + lane];
    float p3 = acc[6] * aS[192 + lane] + acc[7] * aS[224 + lane];
    float q0 = acc[0] * aD[lane]       + acc[1] * aD[lane + 32];
    float q1 = acc[2] * aD[64 + lane]  + acc[3] * aD[96 + lane];
    float q2 = acc[4] * aD[128 + lane] + acc[5] * aD[160 + lane];
    float q3 = acc[6] * aD[192 + lane] + acc[7] * aD[224 + lane];
    p0 = wred(p0); p1 = wred(p1); p2 = wred(p2); p3 = wred(p3);
    q0 = wred(q0); q1 = wred(q1); q2 = wred(q2); q3 = wred(q3);
    if (lane == 0) {
        *(float4*)&g_as1[(size_t)node * 4] = make_float4(p0, p1, p2, p3);
        *(float4*)&g_ad1[(size_t)node * 4] = make_float4(q0, q1, q2, q3);
    }
}

__global__ __launch_bounds__(256) void gat1_gemm_kernel(
        const float* __restrict__ x, const float* __restrict__ W1,
        const float* __restrict__ a_src, const float* __restrict__ a_dst) {
    __shared__ float W1s[FIN * 256];   // 32 KB, k-major
    __shared__ float xs[32 * FIN];     // 32 nodes x 32 feats
    __shared__ float aS[256], aD[256];
    int tid = threadIdx.x, lane = tid & 31, w = tid >> 5;
#pragma unroll
    for (int i = 0; i < 8; i++)
        ((float4*)W1s)[tid + 256 * i] = ((const float4*)W1)[tid + 256 * i];
    aS[tid] = a_src[tid];
    aD[tid] = a_dst[tid];
    int nodeBase = blockIdx.x * 32;
    ((float4*)xs)[tid] = ((const float4*)(x + (size_t)nodeBase * FIN))[tid];
    __syncthreads();
    int n0 = w * 4;                    // node within block
    float acc[4][8];
#pragma unroll
    for (int i = 0; i < 4; i++)
#pragma unroll
        for (int j = 0; j < 8; j++) acc[i][j] = 0.f;
#pragma unroll 4
    for (int k = 0; k < FIN; k++) {
        float xv[4];
#pragma unroll
        for (int i = 0; i < 4; i++) xv[i] = xs[(n0 + i) * FIN + k];
#pragma unroll
        for (int j = 0; j < 8; j++) {
            float wv = W1s[k * 256 + lane + 32 * j];
#pragma unroll
            for (int i = 0; i < 4; i++) acc[i][j] = fmaf(xv[i], wv, acc[i][j]);
        }
    }
#pragma unroll
    for (int i = 0; i < 4; i++)
        gat1_store_alpha(nodeBase + n0 + i, acc[i], aS, aD, lane);
}

// ---------------- GAT layer 1 aggregation: 1 warp/node, 8 cols/lane ---------
// lane covers cols [lane*8, lane*8+8); head = lane>>3 (8 lanes per head).
// csr/asp loads are warp-uniform ONCE per edge; 1 MUFU per lane per edge.
__global__ __launch_bounds__(256) void gat1_agg_kernel(const float* __restrict__ b1) {
    int wid = threadIdx.x >> 5, lane = threadIdx.x & 31;
    int node = blockIdx.x * 8 + wid;
    int beg = g_rowptr[node], end = g_rowptr[node + 1];
    int h = lane >> 3;                 // this lane's head
    const float4* asp4 = (const float4*)g_as1;
    float4 adv = *(const float4*)&g_ad1[(size_t)node * 4];
    float ad = (h < 2) ? (h == 0 ? adv.x : adv.y) : (h == 2 ? adv.z : adv.w);

    float acc[8] = {0,0,0,0,0,0,0,0};
    float ssum = 0.f;
    const float* hb = g_h1 + lane * 8;
    int e = beg;
    for (; e + 1 < end; e += 2) {
        unsigned s0 = (unsigned)__ldg(&g_csr[e]);
        unsigned s1 = (unsigned)__ldg(&g_csr[e + 1]);
        float4 A0 = __ldg(&asp4[s0]);
        float4 A1 = __ldg(&asp4[s1]);
        const float* p0 = hb + s0 * 256u;
        const float* p1 = hb + s1 * 256u;
        float4 u0 = *(const float4*)p0;
        float4 u1 = *(const float4*)(p0 + 4);
        float4 v0 = *(const float4*)p1;
        float4 v1 = *(const float4*)(p1 + 4);
        float a0 = (h < 2) ? (h == 0 ? A0.x : A0.y) : (h == 2 ? A0.z : A0.w);
        float a1 = (h < 2) ? (h == 0 ? A1.x : A1.y) : (h == 2 ? A1.z : A1.w);
        float w0 = eexp(lrelu(a0 + ad));
        float w1 = eexp(lrelu(a1 + ad));
        ssum += w0 + w1;
        acc[0] = fmaf(u0.x, w0, fmaf(v0.x, w1, acc[0]));
        acc[1] = fmaf(u0.y, w0, fmaf(v0.y, w1, acc[1]));
        acc[2] = fmaf(u0.z, w0, fmaf(v0.z, w1, acc[2]));
        acc[3] = fmaf(u0.w, w0, fmaf(v0.w, w1, acc[3]));
        acc[4] = fmaf(u1.x, w0, fmaf(v1.x, w1, acc[4]));
        acc[5] = fmaf(u1.y, w0, fmaf(v1.y, w1, acc[5]));
        acc[6] = fmaf(u1.z, w0, fmaf(v1.z, w1, acc[6]));
        acc[7] = fmaf(u1.w, w0, fmaf(v1.w, w1, acc[7]));
    }
    for (; e < end; ++e) {
        unsigned s0 = (unsigned)__ldg(&g_csr[e]);
        float4 A0 = __ldg(&asp4[s0]);
        const float* p0 = hb + s0 * 256u;
        float4 u0 = *(const float4*)p0;
        float4 u1 = *(const float4*)(p0 + 4);
        float a0 = (h < 2) ? (h == 0 ? A0.x : A0.y) : (h == 2 ? A0.z : A0.w);
        float w0 = eexp(lrelu(a0 + ad));
        ssum += w0;
        acc[0] = fmaf(u0.x, w0, acc[0]);
        acc[1] = fmaf(u0.y, w0, acc[1]);
        acc[2] = fmaf(u0.z, w0, acc[2]);
        acc[3] = fmaf(u0.w, w0, acc[3]);
        acc[4] = fmaf(u1.x, w0, acc[4]);
        acc[5] = fmaf(u1.y, w0, acc[5]);
        acc[6] = fmaf(u1.z, w0, acc[6]);
        acc[7] = fmaf(u1.w, w0, acc[7]);
    }
    float inv = 1.f / (ssum + 1e-16f);
    int c = lane * 8;
    float4 b0 = *(const float4*)&b1[c];
    float4 b4 = *(const float4*)&b1[c + 4];
    float4 o0, o1;
    o0.x = elu1(acc[0] * inv + b0.x);
    o0.y = elu1(acc[1] * inv + b0.y);
    o0.z = elu1(acc[2] * inv + b0.z);
    o0.w = elu1(acc[3] * inv + b0.w);
    o1.x = elu1(acc[4] * inv + b4.x);
    o1.y = elu1(acc[5] * inv + b4.y);
    o1.z = elu1(acc[6] * inv + b4.z);
    o1.w = elu1(acc[7] * inv + b4.w);
    *(float4*)&g_h2in[(size_t)node * 256 + c] = o0;
    *(float4*)&g_h2in[(size_t)node * 256 + c + 4] = o1;
}

// ---------------- GAT layer 2: register-tiled GEMM --------------------------
__global__ __launch_bounds__(256) void gat2_gemm_kernel(const float* __restrict__ W2) {
    extern __shared__ float sm[];
    float* As = sm;                 // 64 x 132
    float* Ws = sm + 64 * 132;      // 64 x 64
    int tid = threadIdx.x;
    int tx = tid & 15, cy = tid >> 4;
    int n0 = blockIdx.x * 128;
    float acc[8][4];
#pragma unroll
    for (int i = 0; i < 8; i++)
#pragma unroll
        for (int j = 0; j < 4; j++) acc[i][j] = 0.f;

    for (int k0 = 0; k0 < 256; k0 += 64) {
#pragma unroll
        for (int i = 0; i < 8; i++) {
            int f = tid + 256 * i;
            int node = f >> 4, kq = f & 15;
            float4 v = *(const float4*)&g_h2in[(size_t)(n0 + node) * 256 + k0 + kq * 4];
            As[(kq * 4 + 0) * 132 + node] = v.x;
            As[(kq * 4 + 1) * 132 + node] = v.y;
            As[(kq * 4 + 2) * 132 + node] = v.z;
            As[(kq * 4 + 3) * 132 + node] = v.w;
        }
#pragma unroll
        for (int i = 0; i < 4; i++) {
            int f = tid + 256 * i;
            int k = f >> 4, cq = f & 15;
            *(float4*)&Ws[k * 64 + cq * 4] = *(const float4*)&W2[(size_t)(k0 + k) * 64 + cq * 4];
        }
        __syncthreads();
#pragma unroll 16
        for (int k = 0; k < 64; k++) {
            float4 a0 = *(float4*)&As[k * 132 + tx * 8];
            float4 a1 = *(float4*)&As[k * 132 + tx * 8 + 4];
            float4 wv = *(float4*)&Ws[k * 64 + cy * 4];
            float av[8] = {a0.x, a0.y, a0.z, a0.w, a1.x, a1.y, a1.z, a1.w};
#pragma unroll
            for (int i = 0; i < 8; i++) {
                acc[i][0] = fmaf(av[i], wv.x, acc[i][0]);
                acc[i][1] = fmaf(av[i], wv.y, acc[i][1]);
                acc[i][2] = fmaf(av[i], wv.z, acc[i][2]);
                acc[i][3] = fmaf(av[i], wv.w, acc[i][3]);
            }
        }
        __syncthreads();
    }
#pragma unroll
    for (int i = 0; i < 8; i++) {
        int node = n0 + tx * 8 + i;
        *(float4*)&g_t2[(size_t)node * 64 + cy * 4] =
            make_float4(acc[i][0], acc[i][1], acc[i][2], acc[i][3]);
    }
}

// ---------------- alpha coefficients for layer 2 ----------------------------
__global__ __launch_bounds__(256) void alpha2_kernel(const float* __restrict__ a_src,
                                                     const float* __restrict__ a_dst) {
    int node = blockIdx.x * 8 + (threadIdx.x >> 5);
    int lane = threadIdx.x & 31;
    float t0 = g_t2[(size_t)node * 64 + lane];
    float t1 = g_t2[(size_t)node * 64 + lane + 32];
    float p = wred(t0 * __ldg(&a_src[lane]) + t1 * __ldg(&a_src[lane + 32]));
    float q = wred(t0 * __ldg(&a_dst[lane]) + t1 * __ldg(&a_dst[lane + 32]));
    if (lane == 0) { g_as2[node] = p; g_ad2[node] = q; }
}

// ---------------- GAT layer 2 aggregation: single pass ----------------------
__global__ __launch_bounds__(256) void gat2_agg_kernel(const float* __restrict__ b2) {
    int node = blockIdx.x * 8 + (threadIdx.x >> 5);
    int lane = threadIdx.x & 31;
    int beg = g_rowptr[node], end = g_rowptr[node + 1];
    float ad = g_ad2[node];
    float2 acc = make_float2(0.f, 0.f);
    float ssum = 0.f;
    const float* tb = g_t2 + lane * 2;
    int e = beg;
    for (; e + 3 < end; e += 4) {
        unsigned s0 = (unsigned)__ldg(&g_csr[e]);
        unsigned s1 = (unsigned)__ldg(&g_csr[e + 1]);
        unsigned s2 = (unsigned)__ldg(&g_csr[e + 2]);
        unsigned s3 = (unsigned)__ldg(&g_csr[e + 3]);
        float a0 = __ldg(&g_as2[s0]);
        float a1 = __ldg(&g_as2[s1]);
        float a2 = __ldg(&g_as2[s2]);
        float a3 = __ldg(&g_as2[s3]);
        float2 v0 = *(const float2*)(tb + s0 * 64u);
        float2 v1 = *(const float2*)(tb + s1 * 64u);
        float2 v2 = *(const float2*)(tb + s2 * 64u);
        float2 v3 = *(const float2*)(tb + s3 * 64u);
        float w0 = eexp(lrelu(a0 + ad));
        float w1 = eexp(lrelu(a1 + ad));
        float w2 = eexp(lrelu(a2 + ad));
        float w3 = eexp(lrelu(a3 + ad));
        ssum += (w0 + w1) + (w2 + w3);
        acc.x = fmaf(v0.x, w0, fmaf(v1.x, w1, fmaf(v2.x, w2, fmaf(v3.x, w3, acc.x))));
        acc.y = fmaf(v0.y, w0, fmaf(v1.y, w1, fmaf(v2.y, w2, fmaf(v3.y, w3, acc.y))));
    }
    for (; e < end; ++e) {
        unsigned s0 = (unsigned)__ldg(&g_csr[e]);
        float w0 = eexp(lrelu(__ldg(&g_as2[s0]) + ad));
        float2 v0 = *(const float2*)(tb + s0 * 64u);
        ssum += w0;
        acc.x = fmaf(v0.x, w0, acc.x);
        acc.y = fmaf(v0.y, w0, acc.y);
    }
    float inv = 1.f / (ssum + 1e-16f);
    int c = lane * 2;
    float2 bv = *(const float2*)&b2[c];
    float2 o;
    o.x = elu1(acc.x * inv + bv.x);
    o.y = elu1(acc.y * inv + bv.y);
    *(float2*)&g_seqin[(size_t)node * 64 + c] = o;
}

// ---------------- GRU L0 input GEMM: register-tiled -------------------------
__global__ __launch_bounds__(256) void gru_in_gemm_kernel(const float* __restrict__ Wih,
                                                          const float* __restrict__ bih) {
    extern __shared__ float sm[];
    float* As = sm;
    float* Ws = sm + 64 * 132;
    int tid = threadIdx.x;
    int tx = tid & 15, cy = tid >> 4;
    int n0 = blockIdx.x * 128;
    int j0 = blockIdx.y * 64;

#pragma unroll
    for (int i = 0; i < 8; i++) {
        int f = tid + 256 * i;
        int node = f >> 4, kq = f & 15;
        float4 v = *(const float4*)&g_seqin[(size_t)(n0 + node) * 64 + kq * 4];
        As[(kq * 4 + 0) * 132 + node] = v.x;
        As[(kq * 4 + 1) * 132 + node] = v.y;
        As[(kq * 4 + 2) * 132 + node] = v.z;
        As[(kq * 4 + 3) * 132 + node] = v.w;
    }
#pragma unroll
    for (int i = 0; i < 4; i++) {
        int f = tid + 256 * i;
        int j = f >> 4, kq = f & 15;
        float4 v = *(const float4*)&Wih[(size_t)(j0 + j) * 64 + kq * 4];
        Ws[(kq * 4 + 0) * 64 + j] = v.x;
        Ws[(kq * 4 + 1) * 64 + j] = v.y;
        Ws[(kq * 4 + 2) * 64 + j] = v.z;
        Ws[(kq * 4 + 3) * 64 + j] = v.w;
    }
    __syncthreads();

    float acc[8][4];
#pragma unroll
    for (int i = 0; i < 8; i++)
#pragma unroll
        for (int j = 0; j < 4; j++) acc[i][j] = 0.f;
#pragma unroll 16
    for (int k = 0; k < 64; k++) {
        float4 a0 = *(float4*)&As[k * 132 + tx * 8];
        float4 a1 = *(float4*)&As[k * 132 + tx * 8 + 4];
        float4 wv = *(float4*)&Ws[k * 64 + cy * 4];
        float av[8] = {a0.x, a0.y, a0.z, a0.w, a1.x, a1.y, a1.z, a1.w};
#pragma unroll
        for (int i = 0; i < 8; i++) {
            acc[i][0] = fmaf(av[i], wv.x, acc[i][0]);
            acc[i][1] = fmaf(av[i], wv.y, acc[i][1]);
            acc[i][2] = fmaf(av[i], wv.z, acc[i][2]);
            acc[i][3] = fmaf(av[i], wv.w, acc[i][3]);
        }
    }
    float4 bv = *(const float4*)&bih[j0 + cy * 4];
#pragma unroll
    for (int i = 0; i < 8; i++) {
        int node = n0 + tx * 8 + i;
        *(float4*)&g_gi[(size_t)node * 192 + j0 + cy * 4] =
            make_float4(acc[i][0] + bv.x, acc[i][1] + bv.y,
                        acc[i][2] + bv.z, acc[i][3] + bv.w);
    }
}

// ---------------- Fused 2-layer GRU, TWO graphs per CTA ---------------------
// 32 CTAs x 192 threads. Each thread owns 3 adjacent rows (same as R11) but
// runs the dot for BOTH graphs each round using the SAME register-resident
// weights. One round = dotA + dotB + barrier + combines(A.h0, B.h0, A.h1,
// B.h1 spread over all 192 threads) + barrier. The ~650-cyc fixed per-step
// overhead is amortized over 2 graph-steps.
__global__ __launch_bounds__(192, 1) void gru_fused_kernel(
        const float* __restrict__ Whh0, const float* __restrict__ bhh0,
        const float* __restrict__ Wih1, const float* __restrict__ bih1,
        const float* __restrict__ Whh1, const float* __restrict__ bhh1,
        const float* __restrict__ Wl,   const float* __restrict__ bl,
        float* __restrict__ outp) {
    __shared__ __align__(16) float S[2][576];
    __shared__ __align__(16) float gis[2][192];
    __shared__ __align__(16) float h0s[2][64];
    __shared__ __align__(16) float h1s[2][64];

    int tid = threadIdx.x;
    int gA = blockIdx.x * 2, gB = gA + 1;
    int r0 = tid * 3;                  // rows r0..r0+2 (never straddle a matrix)

    const float* wbase;
    float bias0, bias1, bias2;
    bool useH0 = (r0 < 384);
    if (r0 < 192) {
        wbase = Whh0 + (size_t)r0 * 64;
        bias0 = bhh0[r0]; bias1 = bhh0[r0 + 1]; bias2 = bhh0[r0 + 2];
    } else if (r0 < 384) {
        int q = r0 - 192;
        wbase = Wih1 + (size_t)q * 64;
        bias0 = bih1[q]; bias1 = bih1[q + 1]; bias2 = bih1[q + 2];
    } else {
        int q = r0 - 384;
        wbase = Whh1 + (size_t)q * 64;
        bias0 = bhh1[q]; bias1 = bhh1[q + 1]; bias2 = bhh1[q + 2];
    }

    unsigned long long wA[32], wB[32], wC[32];
    {
        const unsigned long long* wp = (const unsigned long long*)wbase;
#pragma unroll
        for (int i = 0; i < 32; i++) wA[i] = wp[i];
#pragma unroll
        for (int i = 0; i < 32; i++) wB[i] = wp[32 + i];
#pragma unroll
        for (int i = 0; i < 32; i++) wC[i] = wp[64 + i];
    }

    if (tid < 64) {
        h0s[0][tid] = 0.f; h0s[1][tid] = 0.f;
        h1s[0][tid] = 0.f; h1s[1][tid] = 0.f;
    }

    const float* giA = g_gi + (size_t)gA * 512 * 192;
    const float* giB = g_gi + (size_t)gB * 512 * 192;
    float giAc = giA[tid], giBc = giB[tid];
    __syncthreads();

    const ulonglong2* hvA = (const ulonglong2*)(useH0 ? h0s[0] : h1s[0]);
    const ulonglong2* hvB = (const ulonglong2*)(useH0 ? h0s[1] : h1s[1]);

    for (int t = 0; t <= 512; t++) {
        gis[0][tid] = giAc;
        gis[1][tid] = giBc;
        {
            int tn = (t + 1 < 512) ? (t + 1) : 511;
            giAc = giA[(size_t)tn * 192 + tid];
            giBc = giB[(size_t)tn * 192 + tid];
        }
        // dot for graph A
        {
            unsigned long long a0 = 0, a1 = 0, b0 = 0, b1 = 0, c0 = 0, c1 = 0;
#pragma unroll
            for (int m = 0; m < 16; m++) {
                ulonglong2 hh = hvA[m];
                fma2(a0, wA[2 * m],     hh.x);
                fma2(a1, wA[2 * m + 1], hh.y);
                fma2(b0, wB[2 * m],     hh.x);
                fma2(b1, wB[2 * m + 1], hh.y);
                fma2(c0, wC[2 * m],     hh.x);
                fma2(c1, wC[2 * m + 1], hh.y);
            }
            S[0][r0]     = unpack_sum(a0) + unpack_sum(a1) + bias0;
            S[0][r0 + 1] = unpack_sum(b0) + unpack_sum(b1) + bias1;
            S[0][r0 + 2] = unpack_sum(c0) + unpack_sum(c1) + bias2;
        }
        // dot for graph B
        {
            unsigned long long a0 = 0, a1 = 0, b0 = 0, b1 = 0, c0 = 0, c1 = 0;
#pragma unroll
            for (int m = 0; m < 16; m++) {
                ulonglong2 hh = hvB[m];
                fma2(a0, wA[2 * m],     hh.x);
                fma2(a1, wA[2 * m + 1], hh.y);
                fma2(b0, wB[2 * m],     hh.x);
                fma2(b1, wB[2 * m + 1], hh.y);
                fma2(c0, wC[2 * m],     hh.x);
                fma2(c1, wC[2 * m + 1], hh.y);
            }
            S[1][r0]     = unpack_sum(a0) + unpack_sum(a1) + bias0;
            S[1][r0 + 1] = unpack_sum(b0) + unpack_sum(b1) + bias1;
            S[1][r0 + 2] = unpack_sum(c0) + unpack_sum(c1) + bias2;
        }
        __syncthreads();

        if (t < 512) {
            if (tid < 64) {            // A.h0[t]
                float r = sigm(gis[0][tid] + S[0][tid]);
                float z = sigm(gis[0][64 + tid] + S[0][64 + tid]);
                float n = tanhap(gis[0][128 + tid] + r * S[0][128 + tid]);
                h0s[0][tid] = (1.f - z) * n + z * h0s[0][tid];
            } else if (tid < 128) {    // B.h0[t]
                int j = tid - 64;
                float r = sigm(gis[1][j] + S[1][j]);
                float z = sigm(gis[1][64 + j] + S[1][64 + j]);
                float n = tanhap(gis[1][128 + j] + r * S[1][128 + j]);
                h0s[1][j] = (1.f - z) * n + z * h0s[1][j];
            }
        }
        if (t >= 1) {
            if (tid >= 128) {          // A.h1[t-1]
                int j = tid - 128;
                float r = sigm(S[0][192 + j] + S[0][384 + j]);
                float z = sigm(S[0][256 + j] + S[0][448 + j]);
                float n = tanhap(S[0][320 + j] + r * S[0][512 + j]);
                h1s[0][j] = (1.f - z) * n + z * h1s[0][j];
            } else if (tid < 64) {     // B.h1[t-1] (second job for tid<64)
                int j = tid;
                float r = sigm(S[1][192 + j] + S[1][384 + j]);
                float z = sigm(S[1][256 + j] + S[1][448 + j]);
                float n = tanhap(S[1][320 + j] + r * S[1][512 + j]);
                h1s[1][j] = (1.f - z) * n + z * h1s[1][j];
            }
        }
        __syncthreads();
    }

    if (tid < OUTD) {
        float acc = bl[tid];
        const float* wr = Wl + tid * 64;
#pragma unroll 8
        for (int k = 0; k < 64; k++) acc = fmaf(h1s[0][k], wr[k], acc);
        outp[gA * OUTD + tid] = acc;
    } else if (tid >= 64 && tid < 64 + OUTD) {
        int o = tid - 64;
        float acc = bl[o];
        const float* wr = Wl + o * 64;
#pragma unroll 8
        for (int k = 0; k < 64; k++) acc = fmaf(h1s[1][k], wr[k], acc);
        outp[gB * OUTD + o] = acc;
    }
}

// ---------------- launch ----------------
extern "C" void kernel_launch(void* const* d_in, const int* in_sizes, int n_in,
                              void* d_out, int out_size) {
    const float* x      = (const float*)d_in[0];
    const int*   ei     = (const int*)d_in[1];
    const float* W1     = (const float*)d_in[3];
    const float* a_src1 = (const float*)d_in[4];
    const float* a_dst1 = (const float*)d_in[5];
    const float* b1     = (const float*)d_in[6];
    const float* W2     = (const float*)d_in[7];
    const float* a_src2 = (const float*)d_in[8];
    const float* a_dst2 = (const float*)d_in[9];
    const float* b2     = (const float*)d_in[10];
    const float* Wih0   = (const float*)d_in[11];
    const float* Whh0   = (const float*)d_in[12];
    const float* bih0   = (const float*)d_in[13];
    const float* bhh0   = (const float*)d_in[14];
    const float* Wih1   = (const float*)d_in[15];
    const float* Whh1   = (const float*)d_in[16];
    const float* bih1   = (const float*)d_in[17];
    const float* bhh1   = (const float*)d_in[18];
    const float* Wl     = (const float*)d_in[19];
    const float* bl     = (const float*)d_in[20];
    float* out = (float*)d_out;

    cudaFuncSetAttribute(gat2_gemm_kernel,
                         cudaFuncAttributeMaxDynamicSharedMemorySize, 50176);
    cudaFuncSetAttribute(gru_in_gemm_kernel,
                         cudaFuncAttributeMaxDynamicSharedMemorySize, 50176);

    hist_scan_kernel<<<ET / 1024, 1024>>>(ei);                         // 1
    scatter_kernel<<<2176, 256>>>(ei);                                 // 2
    gat1_gemm_kernel<<<1024, 256>>>(x, W1, a_src1, a_dst1);            // 3
    gat1_agg_kernel<<<4096, 256>>>(b1);                                // 4 <- ncu slot
    gat2_gemm_kernel<<<256, 256, 50176>>>(W2);                         // 5
    alpha2_kernel<<<4096, 256>>>(a_src2, a_dst2);                      // 6
    gat2_agg_kernel<<<4096, 256>>>(b2);                                // 7
    gru_in_gemm_kernel<<<dim3(256, 3), 256, 50176>>>(Wih0, bih0);      // 8
    gru_fused_kernel<<<32, 192>>>(Whh0, bhh0, Wih1, bih1, Whh1, bhh1,
                                  Wl, bl, out);                        // 9
}

// round 13
// speedup vs baseline: 1.8004x; 1.8004x over previous
#include <cuda_runtime.h>
#include <cuda_bf16.h>

#define NN    32768
#define FIN   32
#define HC    64
#define HEADS 4
#define EE    524288
#define ET    (EE + NN)     // 557056 edges incl. self-loops
#define BATCH 64
#define TT    512
#define OUTD  24

// ---------------- scratch (device globals; no allocation) ----------------
__device__ __align__(16) float g_h1[(size_t)NN * 256];     // GAT1 GEMM out
__device__ __align__(16) float g_h2in[(size_t)NN * 256];   // GAT1 agg + b1 + elu
__device__ __align__(16) float g_t2[(size_t)NN * 64];      // GAT2 GEMM out
__device__ __align__(16) float g_seqin[(size_t)NN * 64];   // GAT2 agg + b2 + elu
__device__ __align__(16) float g_gi[(size_t)NN * 192];     // GRU L0 input gates
__device__ __align__(16) float g_as1[NN * 4];
__device__ __align__(16) float g_ad1[NN * 4];
__device__ float g_as2[NN];
__device__ float g_ad2[NN];
__device__ int   g_deg[NN];
__device__ int   g_rowptr[NN + 1];
__device__ int   g_cursor[NN];
__device__ int   g_csr[ET];
__device__ unsigned g_hist_done;

// ---------------- helpers ----------------
__device__ __forceinline__ float lrelu(float v)  { return v > 0.f ? v : 0.2f * v; }
__device__ __forceinline__ float elu1(float v)   { return v > 0.f ? v : (__expf(v) - 1.f); }
// fast tanh (MUFU), |rel err| ~2^-11 << 1e-3 budget
__device__ __forceinline__ float tanhap(float x) {
    float y; asm("tanh.approx.f32 %0, %1;" : "=f"(y) : "f"(x)); return y;
}
__device__ __forceinline__ float sigm(float v)   { return 0.5f * tanhap(0.5f * v) + 0.5f; }
// clamped exp: attention logits are small here; clamp guards overflow only.
__device__ __forceinline__ float eexp(float v)   { return __expf(fminf(v, 60.f)); }

__device__ __forceinline__ float wred(float v) {
#pragma unroll
    for (int o = 16; o; o >>= 1) v += __shfl_xor_sync(0xffffffffu, v, o);
    return v;
}

// packed fp32x2 FMA (sm_103a FFMA2)
__device__ __forceinline__ void fma2(unsigned long long& acc,
                                     unsigned long long a, unsigned long long b) {
    asm("fma.rn.f32x2 %0, %1, %2, %0;" : "+l"(acc) : "l"(a), "l"(b));
}
__device__ __forceinline__ float unpack_sum(unsigned long long v) {
    unsigned lo = (unsigned)v, hi = (unsigned)(v >> 32);
    return __uint_as_float(lo) + __uint_as_float(hi);
}

// ---------------- CSR build: hist + (last block) scan, fused ----------------
__global__ __launch_bounds__(1024) void hist_scan_kernel(const int* __restrict__ ei) {
    int i = blockIdx.x * 1024 + threadIdx.x;       // ET == 544*1024 exactly
    int dst = (i < EE) ? ei[EE + i] : (i - EE);
    atomicAdd(&g_deg[dst], 1);
    __threadfence();
    __shared__ unsigned isLast;
    __shared__ int wsum[32];
    if (threadIdx.x == 0) {
        unsigned v = atomicAdd(&g_hist_done, 1u);
        isLast = (v == gridDim.x - 1) ? 1u : 0u;
    }
    __syncthreads();
    if (!isLast) return;
    if (threadIdx.x == 0) g_hist_done = 0;

    int tid = threadIdx.x;
    int vals[32];
    int base = tid * 32;
    int s = 0;
#pragma unroll
    for (int j = 0; j < 32; j++) {
        int v = g_deg[base + j];
        g_deg[base + j] = 0;
        vals[j] = v; s += v;
    }
    int lane = tid & 31, wid = tid >> 5;
    int inc = s;
#pragma unroll
    for (int o = 1; o < 32; o <<= 1) {
        int y = __shfl_up_sync(0xffffffffu, inc, o);
        if (lane >= o) inc += y;
    }
    if (lane == 31) wsum[wid] = inc;
    __syncthreads();
    if (wid == 0) {
        int v = wsum[lane];
#pragma unroll
        for (int o = 1; o < 32; o <<= 1) {
            int y = __shfl_up_sync(0xffffffffu, v, o);
            if (lane >= o) v += y;
        }
        wsum[lane] = v;
    }
    __syncthreads();
    int off = inc - s + (wid > 0 ? wsum[wid - 1] : 0);
#pragma unroll
    for (int j = 0; j < 32; j++) {
        g_rowptr[base + j] = off;
        g_cursor[base + j] = off;
        off += vals[j];
    }
    if (tid == 1023) g_rowptr[NN] = off;
}

__global__ void scatter_kernel(const int* __restrict__ ei) {
    int i = blockIdx.x * blockDim.x + threadIdx.x;
    if (i >= ET) return;
    int src, dst;
    if (i < EE) { src = ei[i]; dst = ei[EE + i]; }
    else        { src = dst = i - EE; }
    int pos = atomicAdd(&g_cursor[dst], 1);
    g_csr[pos] = src;
}

// ---------------- GAT layer 1: GEMM (4 nodes/warp) + attention coeffs -------
__device__ __forceinline__ void gat1_store_alpha(int node, const float acc[8],
                                                 const float* aS, const float* aD, int lane) {
#pragma unroll
    for (int j = 0; j < 8; j++) g_h1[(size_t)node * 256 + lane + 32 * j] = acc[j];
    float p0 = acc[0] * aS[lane]       + acc[1] * aS[lane + 32];
    float p1 = acc[2] * aS[64 + lane]  + acc[3] * aS[96 + lane];
    float p2 = acc[4] * aS[128 + lane] + acc[5] * aS[160 + lane];
    float p3 = acc[6] * aS[192 + lane] + acc[7] * aS[224 + lane];
    float q0 = acc[0] * aD[lane]       + acc[1] * aD[lane + 32];
    float q1 = acc[2] * aD[64 + lane]  + acc[3] * aD[96 + lane];
    float q2 = acc[4] * aD[128 + lane] + acc[5] * aD[160 + lane];
    float q3 = acc[6] * aD[192 + lane] + acc[7] * aD[224 + lane];
    p0 = wred(p0); p1 = wred(p1); p2 = wred(p2); p3 = wred(p3);
    q0 = wred(q0); q1 = wred(q1); q2 = wred(q2); q3 = wred(q3);
    if (lane == 0) {
        *(float4*)&g_as1[(size_t)node * 4] = make_float4(p0, p1, p2, p3);
        *(float4*)&g_ad1[(size_t)node * 4] = make_float4(q0, q1, q2, q3);
    }
}

__global__ __launch_bounds__(256) void gat1_gemm_kernel(
        const float* __restrict__ x, const float* __restrict__ W1,
        const float* __restrict__ a_src, const float* __restrict__ a_dst) {
    __shared__ float W1s[FIN * 256];   // 32 KB, k-major
    __shared__ float xs[32 * FIN];     // 32 nodes x 32 feats
    __shared__ float aS[256], aD[256];
    int tid = threadIdx.x, lane = tid & 31, w = tid >> 5;
#pragma unroll
    for (int i = 0; i < 8; i++)
        ((float4*)W1s)[tid + 256 * i] = ((const float4*)W1)[tid + 256 * i];
    aS[tid] = a_src[tid];
    aD[tid] = a_dst[tid];
    int nodeBase = blockIdx.x * 32;
    ((float4*)xs)[tid] = ((const float4*)(x + (size_t)nodeBase * FIN))[tid];
    __syncthreads();
    int n0 = w * 4;                    // node within block
    float acc[4][8];
#pragma unroll
    for (int i = 0; i < 4; i++)
#pragma unroll
        for (int j = 0; j < 8; j++) acc[i][j] = 0.f;
#pragma unroll 4
    for (int k = 0; k < FIN; k++) {
        float xv[4];
#pragma unroll
        for (int i = 0; i < 4; i++) xv[i] = xs[(n0 + i) * FIN + k];
#pragma unroll
        for (int j = 0; j < 8; j++) {
            float wv = W1s[k * 256 + lane + 32 * j];
#pragma unroll
            for (int i = 0; i < 4; i++) acc[i][j] = fmaf(xv[i], wv, acc[i][j]);
        }
    }
#pragma unroll
    for (int i = 0; i < 4; i++)
        gat1_store_alpha(nodeBase + n0 + i, acc[i], aS, aD, lane);
}

// ---------------- GAT layer 1 aggregation: 2 warps/node, float4 lanes -------
__global__ __launch_bounds__(256) void gat1_agg_kernel(const float* __restrict__ b1) {
    int wid = threadIdx.x >> 5, lane = threadIdx.x & 31;
    int node = blockIdx.x * 4 + (wid >> 1);
    int half = wid & 1;
    int beg = g_rowptr[node], end = g_rowptr[node + 1];
    const float2* asp = (const float2*)g_as1;
    float2 adv = ((const float2*)g_ad1)[node * 2 + half];
    bool lo = lane < 16;
    float ad = lo ? adv.x : adv.y;

    float4 acc = make_float4(0.f, 0.f, 0.f, 0.f);
    float ssum = 0.f;
    const float* hb = g_h1 + half * 128 + lane * 4;
    int e = beg;
    for (; e + 3 < end; e += 4) {
        unsigned s0 = (unsigned)__ldg(&g_csr[e]);
        unsigned s1 = (unsigned)__ldg(&g_csr[e + 1]);
        unsigned s2 = (unsigned)__ldg(&g_csr[e + 2]);
        unsigned s3 = (unsigned)__ldg(&g_csr[e + 3]);
        float2 A0 = __ldg(&asp[s0 * 2u + half]);
        float2 A1 = __ldg(&asp[s1 * 2u + half]);
        float2 A2 = __ldg(&asp[s2 * 2u + half]);
        float2 A3 = __ldg(&asp[s3 * 2u + half]);
        float4 v0 = *(const float4*)(hb + s0 * 256u);
        float4 v1 = *(const float4*)(hb + s1 * 256u);
        float4 v2 = *(const float4*)(hb + s2 * 256u);
        float4 v3 = *(const float4*)(hb + s3 * 256u);
        float w0 = eexp(lrelu((lo ? A0.x : A0.y) + ad));
        float w1 = eexp(lrelu((lo ? A1.x : A1.y) + ad));
        float w2 = eexp(lrelu((lo ? A2.x : A2.y) + ad));
        float w3 = eexp(lrelu((lo ? A3.x : A3.y) + ad));
        ssum += (w0 + w1) + (w2 + w3);
        acc.x = fmaf(v0.x, w0, fmaf(v1.x, w1, fmaf(v2.x, w2, fmaf(v3.x, w3, acc.x))));
        acc.y = fmaf(v0.y, w0, fmaf(v1.y, w1, fmaf(v2.y, w2, fmaf(v3.y, w3, acc.y))));
        acc.z = fmaf(v0.z, w0, fmaf(v1.z, w1, fmaf(v2.z, w2, fmaf(v3.z, w3, acc.z))));
        acc.w = fmaf(v0.w, w0, fmaf(v1.w, w1, fmaf(v2.w, w2, fmaf(v3.w, w3, acc.w))));
    }
    for (; e < end; ++e) {
        unsigned s0 = (unsigned)__ldg(&g_csr[e]);
        float2 A0 = __ldg(&asp[s0 * 2u + half]);
        float4 v0 = *(const float4*)(hb + s0 * 256u);
        float w0 = eexp(lrelu((lo ? A0.x : A0.y) + ad));
        ssum += w0;
        acc.x = fmaf(v0.x, w0, acc.x);
        acc.y = fmaf(v0.y, w0, acc.y);
        acc.z = fmaf(v0.z, w0, acc.z);
        acc.w = fmaf(v0.w, w0, acc.w);
    }
    float inv = 1.f / (ssum + 1e-16f);
    int c = half * 128 + lane * 4;
    float4 bv = *(const float4*)&b1[c];
    float4 o;
    o.x = elu1(acc.x * inv + bv.x);
    o.y = elu1(acc.y * inv + bv.y);
    o.z = elu1(acc.z * inv + bv.z);
    o.w = elu1(acc.w * inv + bv.w);
    *(float4*)&g_h2in[(size_t)node * 256 + c] = o;
}

// ---------------- GAT layer 2: register-tiled GEMM + fused alpha2 -----------
__global__ __launch_bounds__(256) void gat2_gemm_kernel(
        const float* __restrict__ W2, const float* __restrict__ a_src,
        const float* __restrict__ a_dst) {
    extern __shared__ float sm[];
    float* As = sm;                 // 64 x 132
    float* Ws = sm + 64 * 132;      // 64 x 64
    __shared__ float pS[128][17];
    __shared__ float pD[128][17];
    int tid = threadIdx.x;
    int tx = tid & 15, cy = tid >> 4;
    int n0 = blockIdx.x * 128;
    float acc[8][4];
#pragma unroll
    for (int i = 0; i < 8; i++)
#pragma unroll
        for (int j = 0; j < 4; j++) acc[i][j] = 0.f;

    for (int k0 = 0; k0 < 256; k0 += 64) {
#pragma unroll
        for (int i = 0; i < 8; i++) {
            int f = tid + 256 * i;
            int node = f >> 4, kq = f & 15;
            float4 v = *(const float4*)&g_h2in[(size_t)(n0 + node) * 256 + k0 + kq * 4];
            As[(kq * 4 + 0) * 132 + node] = v.x;
            As[(kq * 4 + 1) * 132 + node] = v.y;
            As[(kq * 4 + 2) * 132 + node] = v.z;
            As[(kq * 4 + 3) * 132 + node] = v.w;
        }
#pragma unroll
        for (int i = 0; i < 4; i++) {
            int f = tid + 256 * i;
            int k = f >> 4, cq = f & 15;
            *(float4*)&Ws[k * 64 + cq * 4] = *(const float4*)&W2[(size_t)(k0 + k) * 64 + cq * 4];
        }
        __syncthreads();
#pragma unroll 16
        for (int k = 0; k < 64; k++) {
            float4 a0 = *(float4*)&As[k * 132 + tx * 8];
            float4 a1 = *(float4*)&As[k * 132 + tx * 8 + 4];
            float4 wv = *(float4*)&Ws[k * 64 + cy * 4];
            float av[8] = {a0.x, a0.y, a0.z, a0.w, a1.x, a1.y, a1.z, a1.w};
#pragma unroll
            for (int i = 0; i < 8; i++) {
                acc[i][0] = fmaf(av[i], wv.x, acc[i][0]);
                acc[i][1] = fmaf(av[i], wv.y, acc[i][1]);
                acc[i][2] = fmaf(av[i], wv.z, acc[i][2]);
                acc[i][3] = fmaf(av[i], wv.w, acc[i][3]);
            }
        }
        __syncthreads();
    }
    float4 as4 = *(const float4*)&a_src[cy * 4];
    float4 ad4 = *(const float4*)&a_dst[cy * 4];
#pragma unroll
    for (int i = 0; i < 8; i++) {
        int nl = tx * 8 + i;
        *(float4*)&g_t2[(size_t)(n0 + nl) * 64 + cy * 4] =
            make_float4(acc[i][0], acc[i][1], acc[i][2], acc[i][3]);
        pS[nl][cy] = acc[i][0] * as4.x + acc[i][1] * as4.y
                   + acc[i][2] * as4.z + acc[i][3] * as4.w;
        pD[nl][cy] = acc[i][0] * ad4.x + acc[i][1] * ad4.y
                   + acc[i][2] * ad4.z + acc[i][3] * ad4.w;
    }
    __syncthreads();
    if (tid < 128) {
        float s = 0.f, d = 0.f;
#pragma unroll
        for (int k = 0; k < 16; k++) { s += pS[tid][k]; d += pD[tid][k]; }
        g_as2[n0 + tid] = s;
        g_ad2[n0 + tid] = d;
    }
}

// ---------------- GAT layer 2 aggregation: single pass ----------------------
__global__ __launch_bounds__(256) void gat2_agg_kernel(const float* __restrict__ b2) {
    int node = blockIdx.x * 8 + (threadIdx.x >> 5);
    int lane = threadIdx.x & 31;
    int beg = g_rowptr[node], end = g_rowptr[node + 1];
    float ad = g_ad2[node];
    float2 acc = make_float2(0.f, 0.f);
    float ssum = 0.f;
    const float* tb = g_t2 + lane * 2;
    int e = beg;
    for (; e + 3 < end; e += 4) {
        unsigned s0 = (unsigned)__ldg(&g_csr[e]);
        unsigned s1 = (unsigned)__ldg(&g_csr[e + 1]);
        unsigned s2 = (unsigned)__ldg(&g_csr[e + 2]);
        unsigned s3 = (unsigned)__ldg(&g_csr[e + 3]);
        float a0 = __ldg(&g_as2[s0]);
        float a1 = __ldg(&g_as2[s1]);
        float a2 = __ldg(&g_as2[s2]);
        float a3 = __ldg(&g_as2[s3]);
        float2 v0 = *(const float2*)(tb + s0 * 64u);
        float2 v1 = *(const float2*)(tb + s1 * 64u);
        float2 v2 = *(const float2*)(tb + s2 * 64u);
        float2 v3 = *(const float2*)(tb + s3 * 64u);
        float w0 = eexp(lrelu(a0 + ad));
        float w1 = eexp(lrelu(a1 + ad));
        float w2 = eexp(lrelu(a2 + ad));
        float w3 = eexp(lrelu(a3 + ad));
        ssum += (w0 + w1) + (w2 + w3);
        acc.x = fmaf(v0.x, w0, fmaf(v1.x, w1, fmaf(v2.x, w2, fmaf(v3.x, w3, acc.x))));
        acc.y = fmaf(v0.y, w0, fmaf(v1.y, w1, fmaf(v2.y, w2, fmaf(v3.y, w3, acc.y))));
    }
    for (; e < end; ++e) {
        unsigned s0 = (unsigned)__ldg(&g_csr[e]);
        float w0 = eexp(lrelu(__ldg(&g_as2[s0]) + ad));
        float2 v0 = *(const float2*)(tb + s0 * 64u);
        ssum += w0;
        acc.x = fmaf(v0.x, w0, acc.x);
        acc.y = fmaf(v0.y, w0, acc.y);
    }
    float inv = 1.f / (ssum + 1e-16f);
    int c = lane * 2;
    float2 bv = *(const float2*)&b2[c];
    float2 o;
    o.x = elu1(acc.x * inv + bv.x);
    o.y = elu1(acc.y * inv + bv.y);
    *(float2*)&g_seqin[(size_t)node * 64 + c] = o;
}

// ---------------- GRU L0 input GEMM: register-tiled -------------------------
__global__ __launch_bounds__(256) void gru_in_gemm_kernel(const float* __restrict__ Wih,
                                                          const float* __restrict__ bih) {
    extern __shared__ float sm[];
    float* As = sm;
    float* Ws = sm + 64 * 132;
    int tid = threadIdx.x;
    int tx = tid & 15, cy = tid >> 4;
    int n0 = blockIdx.x * 128;
    int j0 = blockIdx.y * 64;

#pragma unroll
    for (int i = 0; i < 8; i++) {
        int f = tid + 256 * i;
        int node = f >> 4, kq = f & 15;
        float4 v = *(const float4*)&g_seqin[(size_t)(n0 + node) * 64 + kq * 4];
        As[(kq * 4 + 0) * 132 + node] = v.x;
        As[(kq * 4 + 1) * 132 + node] = v.y;
        As[(kq * 4 + 2) * 132 + node] = v.z;
        As[(kq * 4 + 3) * 132 + node] = v.w;
    }
#pragma unroll
    for (int i = 0; i < 4; i++) {
        int f = tid + 256 * i;
        int j = f >> 4, kq = f & 15;
        float4 v = *(const float4*)&Wih[(size_t)(j0 + j) * 64 + kq * 4];
        Ws[(kq * 4 + 0) * 64 + j] = v.x;
        Ws[(kq * 4 + 1) * 64 + j] = v.y;
        Ws[(kq * 4 + 2) * 64 + j] = v.z;
        Ws[(kq * 4 + 3) * 64 + j] = v.w;
    }
    __syncthreads();

    float acc[8][4];
#pragma unroll
    for (int i = 0; i < 8; i++)
#pragma unroll
        for (int j = 0; j < 4; j++) acc[i][j] = 0.f;
#pragma unroll 16
    for (int k = 0; k < 64; k++) {
        float4 a0 = *(float4*)&As[k * 132 + tx * 8];
        float4 a1 = *(float4*)&As[k * 132 + tx * 8 + 4];
        float4 wv = *(float4*)&Ws[k * 64 + cy * 4];
        float av[8] = {a0.x, a0.y, a0.z, a0.w, a1.x, a1.y, a1.z, a1.w};
#pragma unroll
        for (int i = 0; i < 8; i++) {
            acc[i][0] = fmaf(av[i], wv.x, acc[i][0]);
            acc[i][1] = fmaf(av[i], wv.y, acc[i][1]);
            acc[i][2] = fmaf(av[i], wv.z, acc[i][2]);
            acc[i][3] = fmaf(av[i], wv.w, acc[i][3]);
        }
    }
    float4 bv = *(const float4*)&bih[j0 + cy * 4];
#pragma unroll
    for (int i = 0; i < 8; i++) {
        int node = n0 + tx * 8 + i;
        *(float4*)&g_gi[(size_t)node * 192 + j0 + cy * 4] =
            make_float4(acc[i][0] + bv.x, acc[i][1] + bv.y,
                        acc[i][2] + bv.z, acc[i][3] + bv.w);
    }
}

// ---------------- Fused 2-layer GRU recurrence + head (R11 config) ---------
// 192 threads = 6 warps, 3 adjacent rows/thread of the 576-row stack
// [gh0 | gi1 | gh1]. Two barriers per step. 96 ull weight regs/thread.
__global__ __launch_bounds__(192, 1) void gru_fused_kernel(
        const float* __restrict__ Whh0, const float* __restrict__ bhh0,
        const float* __restrict__ Wih1, const float* __restrict__ bih1,
        const float* __restrict__ Whh1, const float* __restrict__ bhh1,
        const float* __restrict__ Wl,   const float* __restrict__ bl,
        float* __restrict__ outp) {
    __shared__ __align__(16) float S[576];
    __shared__ __align__(16) float gi0s[192];
    __shared__ __align__(16) float h0s[64];
    __shared__ __align__(16) float h1s[64];

    int tid = threadIdx.x;
    int graph = blockIdx.x;
    int r0 = tid * 3;                  // rows r0..r0+2 (same matrix)

    const float* wbase;
    const float* hsrc;
    float bias0, bias1, bias2;
    if (r0 < 192) {
        wbase = Whh0 + (size_t)r0 * 64; hsrc = h0s;
        bias0 = bhh0[r0]; bias1 = bhh0[r0 + 1]; bias2 = bhh0[r0 + 2];
    } else if (r0 < 384) {
        int q = r0 - 192;
        wbase = Wih1 + (size_t)q * 64;  hsrc = h0s;
        bias0 = bih1[q]; bias1 = bih1[q + 1]; bias2 = bih1[q + 2];
    } else {
        int q = r0 - 384;
        wbase = Whh1 + (size_t)q * 64;  hsrc = h1s;
        bias0 = bhh1[q]; bias1 = bhh1[q + 1]; bias2 = bhh1[q + 2];
    }

    unsigned long long wA[32], wB[32], wC[32];
    {
        const unsigned long long* wp = (const unsigned long long*)wbase;
#pragma unroll
        for (int i = 0; i < 32; i++) wA[i] = wp[i];
#pragma unroll
        for (int i = 0; i < 32; i++) wB[i] = wp[32 + i];
#pragma unroll
        for (int i = 0; i < 32; i++) wC[i] = wp[64 + i];
    }

    if (tid < 64) { h0s[tid] = 0.f; h1s[tid] = 0.f; }

    const float* gi = g_gi + (size_t)graph * 512 * 192;
    float gi_cur = gi[tid];
    __syncthreads();

    const ulonglong2* hv = (const ulonglong2*)hsrc;

    for (int t = 0; t <= 512; t++) {
        gi0s[tid] = gi_cur;
        {
            int tn = (t + 1 < 512) ? (t + 1) : 511;
            gi_cur = gi[(size_t)tn * 192 + tid];
        }
        unsigned long long a0 = 0, a1 = 0, b0 = 0, b1 = 0, c0 = 0, c1 = 0;
#pragma unroll
        for (int m = 0; m < 16; m++) {
            ulonglong2 hh = hv[m];
            fma2(a0, wA[2 * m],     hh.x);
            fma2(a1, wA[2 * m + 1], hh.y);
            fma2(b0, wB[2 * m],     hh.x);
            fma2(b1, wB[2 * m + 1], hh.y);
            fma2(c0, wC[2 * m],     hh.x);
            fma2(c1, wC[2 * m + 1], hh.y);
        }
        S[r0]     = unpack_sum(a0) + unpack_sum(a1) + bias0;
        S[r0 + 1] = unpack_sum(b0) + unpack_sum(b1) + bias1;
        S[r0 + 2] = unpack_sum(c0) + unpack_sum(c1) + bias2;
        __syncthreads();

        if (t < 512 && tid < 64) {
            float r = sigm(gi0s[tid] + S[tid]);
            float z = sigm(gi0s[64 + tid] + S[64 + tid]);
            float n = tanhap(gi0s[128 + tid] + r * S[128 + tid]);
            h0s[tid] = (1.f - z) * n + z * h0s[tid];
        }
        if (t >= 1 && tid >= 64 && tid < 128) {
            int j = tid - 64;
            float r = sigm(S[192 + j] + S[384 + j]);
            float z = sigm(S[256 + j] + S[448 + j]);
            float n = tanhap(S[320 + j] + r * S[512 + j]);
            h1s[j] = (1.f - z) * n + z * h1s[j];
        }
        __syncthreads();
    }

    if (tid < OUTD) {
        float acc = bl[tid];
        const float* wr = Wl + tid * 64;
#pragma unroll 8
        for (int k = 0; k < 64; k++) acc = fmaf(h1s[k], wr[k], acc);
        outp[graph * OUTD + tid] = acc;
    }
}

// ---------------- launch ----------------
extern "C" void kernel_launch(void* const* d_in, const int* in_sizes, int n_in,
                              void* d_out, int out_size) {
    const float* x      = (const float*)d_in[0];
    const int*   ei     = (const int*)d_in[1];
    const float* W1     = (const float*)d_in[3];
    const float* a_src1 = (const float*)d_in[4];
    const float* a_dst1 = (const float*)d_in[5];
    const float* b1     = (const float*)d_in[6];
    const float* W2     = (const float*)d_in[7];
    const float* a_src2 = (const float*)d_in[8];
    const float* a_dst2 = (const float*)d_in[9];
    const float* b2     = (const float*)d_in[10];
    const float* Wih0   = (const float*)d_in[11];
    const float* Whh0   = (const float*)d_in[12];
    const float* bih0   = (const float*)d_in[13];
    const float* bhh0   = (const float*)d_in[14];
    const float* Wih1   = (const float*)d_in[15];
    const float* Whh1   = (const float*)d_in[16];
    const float* bih1   = (const float*)d_in[17];
    const float* bhh1   = (const float*)d_in[18];
    const float* Wl     = (const float*)d_in[19];
    const float* bl     = (const float*)d_in[20];
    float* out = (float*)d_out;

    cudaFuncSetAttribute(gat2_gemm_kernel,
                         cudaFuncAttributeMaxDynamicSharedMemorySize, 50176);
    cudaFuncSetAttribute(gru_in_gemm_kernel,
                         cudaFuncAttributeMaxDynamicSharedMemorySize, 50176);

    hist_scan_kernel<<<ET / 1024, 1024>>>(ei);                         // 1
    scatter_kernel<<<2176, 256>>>(ei);                                 // 2
    gat1_gemm_kernel<<<1024, 256>>>(x, W1, a_src1, a_dst1);            // 3
    gat1_agg_kernel<<<8192, 256>>>(b1);                                // 4 <- ncu slot
    gat2_gemm_kernel<<<256, 256, 50176>>>(W2, a_src2, a_dst2);         // 5
    gat2_agg_kernel<<<4096, 256>>>(b2);                                // 6
    gru_in_gemm_kernel<<<dim3(256, 3), 256, 50176>>>(Wih0, bih0);      // 7
    gru_fused_kernel<<<64, 192>>>(Whh0, bhh0, Wih1, bih1, Whh1, bhh1,
                                  Wl, bl, out);                        // 8
}